// round 12
// baseline (speedup 1.0000x reference)
#include <cuda_runtime.h>
#include <math.h>

// Problem constants
#define NC    22            // columns
#define NE    12            // embeddings per column
#define DD    64            // feature dim
#define BB    2048          // batch
#define NPAIR 231           // 22 choose 2
#define NENT  253           // 22 lin/diag entries + 231 pair entries
#define TBL   (NC*NE)       // 264 table rows
#define NBT   8             // b-tiles (main grid.x)
#define BT    (BB/NBT)      // 256 b per tile

typedef unsigned long long ull;

// ---------------- device scratch ----------------
__device__ float g_sp[TBL * DD];            // 0.01*softplus(emb_std), flat [t*DD+d]
__device__ float g_w[DD * NENT * 8];        // per-d lane-duplicated packed weights
__device__ float g_partial[BB * 2 * DD];    // partial[(b*2+k)][d]
__device__ unsigned g_cnt[NBT];             // btile arrival counters (monotonic)

// ---------------- f32x2 packed helpers (sm_100a+) ----------------
__device__ __forceinline__ ull pack2(float lo, float hi) {
    ull r; asm("mov.b64 %0, {%1, %2};" : "=l"(r) : "f"(lo), "f"(hi)); return r;
}
__device__ __forceinline__ void unpack2(ull x, float& lo, float& hi) {
    asm("mov.b64 {%0, %1}, %2;" : "=f"(lo), "=f"(hi) : "l"(x));
}
__device__ __forceinline__ ull fma2(ull a, ull b, ull c) {
    ull r; asm("fma.rn.f32x2 %0, %1, %2, %3;" : "=l"(r) : "l"(a), "l"(b), "l"(c)); return r;
}
__device__ __forceinline__ ull mul2(ull a, ull b) {
    ull r; asm("mul.rn.f32x2 %0, %1, %2;" : "=l"(r) : "l"(a), "l"(b)); return r;
}

__device__ __forceinline__ void softmax5(const float* __restrict__ log_alpha,
                                         float& w0, float& w1, float& w2,
                                         float& w3, float& w4) {
    float la[5], w[5];
    float mx = -1e30f, s = 0.f;
    #pragma unroll
    for (int z = 0; z < 5; z++) { la[z] = __ldg(log_alpha + z); mx = fmaxf(mx, la[z]); }
    #pragma unroll
    for (int z = 0; z < 5; z++) { w[z] = expf(la[z] - mx); s += w[z]; }
    float inv = 1.0f / s;
    w0 = w[0]*inv; w1 = w[1]*inv; w2 = w[2]*inv; w3 = w[3]*inv; w4 = w[4]*inv;
}

// ---------------- prep kernel (unchanged from r10) --------------------------------
#define LIN_B0   0
#define DIAG_B0  88
#define PAIR_B0  99
#define SP_B0    215
#define PBLK     347

__global__ void __launch_bounds__(128)
prep_kernel(const float* __restrict__ W_ops, const float* __restrict__ W_cat,
            const float* __restrict__ log_alpha, const float* __restrict__ emb_std) {
    const int blk = blockIdx.x;
    const int tid = threadIdx.x;

    if (blk >= SP_B0) {                              // softplus table
        int u = (blk - SP_B0) * 128 + tid;           // < TBL*DD = 16896 exactly
        float x = emb_std[u];
        g_sp[u] = 0.01f * (fmaxf(x, 0.0f) + log1pf(expf(-fabsf(x))));
        return;
    }

    float w0, w1, w2, w3, w4;
    softmax5(log_alpha, w0, w1, w2, w3, w4);
    const float2* W2 = reinterpret_cast<const float2*>(W_ops);
    const float2* C2 = reinterpret_cast<const float2*>(W_cat);

    if (blk >= PAIR_B0) {                            // pair weights: one (p,d)/thread
        int t = (blk - PAIR_B0) * 128 + tid;
        if (t >= NPAIR * DD) return;
        int d = t & 63;
        int p = t >> 6;
        int i = 0, rem = p;
        while (rem >= NC - 1 - i) { rem -= NC - 1 - i; i++; }
        int j = i + 1 + rem;

        float2 Mij = W2[((i*NC+j)*4 + 1)*DD + d];
        float2 Mji = W2[((j*NC+i)*4 + 1)*DD + d];
        float2 Xij = W2[((i*NC+j)*4 + 2)*DD + d];
        float2 Xji = W2[((j*NC+i)*4 + 2)*DD + d];
        float2 Nij = W2[((i*NC+j)*4 + 3)*DD + d];
        float2 Nji = W2[((j*NC+i)*4 + 3)*DD + d];
        float wx = w1*(Mij.x+Mji.x);
        float wy = w1*(Mij.y+Mji.y);
        float wz = 0.5f*(w2*(Xij.x+Xji.x) - w3*(Nij.x+Nji.x));
        float ww = 0.5f*(w2*(Xij.y+Xji.y) - w3*(Nij.y+Nji.y));
        float4* dst = reinterpret_cast<float4*>(g_w) + (d*NENT + NC + p) * 2;
        dst[0] = make_float4(wx, wx, wy, wy);
        dst[1] = make_float4(wz, wz, ww, ww);
        return;
    }

    if (blk >= DIAG_B0) {                            // diagonal weights
        int t = (blk - DIAG_B0) * 128 + tid;         // < NC*DD = 1408 exactly
        int d = t & 63;
        int i = t >> 6;
        float2 Mii = W2[((i*NC+i)*4 + 1)*DD + d];
        reinterpret_cast<float4*>(g_w)[(d*NENT + i) * 2 + 1] =
            make_float4(w1*Mii.x, w1*Mii.x, w1*Mii.y, w1*Mii.y);
        return;
    }

    // linear weights: 8-way stream split
    __shared__ float2 ls[8][16];
    {
        const int il = tid & 15;
        const int c  = tid >> 4;                 // stream id
        const int item = blk * 16 + il;          // < 1408 (88*16 exactly)
        const int i = item >> 6;
        const int d = item & 63;

        const float2* base;
        int stride;
        if (c < 6) {
            int o = (c >> 1) == 0 ? 0 : ((c >> 1) == 1 ? 2 : 3);   // op: P,X,N
            if ((c & 1) == 0) { base = W2 + (i*NC*4 + o)*DD + d; stride = 4*DD; }
            else              { base = W2 + (i*4 + o)*DD + d;     stride = NC*4*DD; }
        } else if (c == 6)    { base = C2 + i*NC*2*DD + d;        stride = 2*DD; }
        else                  { base = C2 + i*2*DD + DD + d;      stride = NC*2*DD; }

        float a0 = 0.f, a1 = 0.f;
        #pragma unroll
        for (int j = 0; j < NC; j++) {
            float2 q = base[j * stride];
            a0 += q.x; a1 += q.y;
        }
        float wc = (c < 2) ? w0 : (c < 4 ? 0.5f*w2 : (c < 6 ? 0.5f*w3 : w4));
        ls[c][il] = make_float2(a0 * wc, a1 * wc);
        __syncthreads();
        if (c == 0) {
            float L0 = 0.f, L1 = 0.f;
            #pragma unroll
            for (int s = 0; s < 8; s++) { L0 += ls[s][il].x; L1 += ls[s][il].y; }
            reinterpret_cast<float4*>(g_w)[(d*NENT + i) * 2] =
                make_float4(L0, L0, L1, L1);
        }
    }
}

// ---------------- main kernel: pairwise compute + single-fence reduce tail --------
// grid: (NBT, 64) = (8, 64), 128 threads; 2 b per thread packed f32x2.
// Tail uses the cooperative-groups fence discipline: weak stores ->
// __syncthreads (CTA sync edge) -> tid0-only release fence + atomic;
// consumer: tid0 acquire fence -> __syncthreads -> all threads read.
__global__ void __launch_bounds__(128)
main_kernel(const int* __restrict__ idx, const float* __restrict__ emb_mean,
            const float* __restrict__ v, float* __restrict__ out) {
    const int d  = blockIdx.y;
    const int btile = blockIdx.x;
    const int b0 = btile * BT;
    const int tid = threadIdx.x;

    __shared__ float swt[NENT * 8];
    __shared__ float mean_s[TBL];
    __shared__ float sp_s[TBL];
    __shared__ unsigned isLastS;

    {
        const float4* wp = reinterpret_cast<const float4*>(g_w) + d * NENT * 2;
        float4* s4 = reinterpret_cast<float4*>(swt);
        #pragma unroll
        for (int t = tid; t < NENT * 2; t += 128) s4[t] = wp[t];
        #pragma unroll
        for (int t = tid; t < TBL; t += 128) {
            mean_s[t] = emb_mean[t * DD + d];
            sp_s[t]   = g_sp[t * DD + d];
        }
    }
    __syncthreads();

    const int b  = b0 + tid;
    const int b2 = b + 128;
    const float vlo = v[b  * DD + d];
    const float vhi = v[b2 * DD + d];

    ull e2[NC];
    #pragma unroll
    for (int i = 0; i < NC; i++) {
        int iv  = idx[i * BB + b];
        int iv2 = idx[i * BB + b2];
        float elo = fmaf(sp_s[i * NE + iv],  vlo, mean_s[i * NE + iv]);
        float ehi = fmaf(sp_s[i * NE + iv2], vhi, mean_s[i * NE + iv2]);
        e2[i] = pack2(elo, ehi);
    }

    ull A0 = 0ULL, A1 = 0ULL;
    const ulonglong2* sw2 = reinterpret_cast<const ulonglong2*>(swt);

    #pragma unroll
    for (int i = 0; i < NC; i++) {
        ulonglong2 wl = sw2[i * 2 + 0];
        ulonglong2 wd = sw2[i * 2 + 1];
        ull p2 = mul2(e2[i], e2[i]);
        A0 = fma2(e2[i], wl.x, A0);
        A1 = fma2(e2[i], wl.y, A1);
        A0 = fma2(p2,    wd.x, A0);
        A1 = fma2(p2,    wd.y, A1);
    }

    const ull NEG1 = 0xBF800000BF800000ULL;
    int pi = NC;
    #pragma unroll
    for (int i = 0; i < NC - 1; i++) {
        #pragma unroll
        for (int j = i + 1; j < NC; j++) {
            ulonglong2 wm = sw2[pi * 2 + 0];
            ulonglong2 wa = sw2[pi * 2 + 1];
            pi++;
            ull p2 = mul2(e2[i], e2[j]);
            ull df = fma2(e2[j], NEG1, e2[i]);
            ull ad = df & 0x7FFFFFFF7FFFFFFFULL;
            A0 = fma2(p2, wm.x, A0);
            A1 = fma2(p2, wm.y, A1);
            A0 = fma2(ad, wa.x, A0);
            A1 = fma2(ad, wa.y, A1);
        }
    }

    float a0l, a0h, a1l, a1h;
    unpack2(A0, a0l, a0h);
    unpack2(A1, a1l, a1h);
    g_partial[(b  * 2 + 0) * DD + d] = a0l;
    g_partial[(b  * 2 + 1) * DD + d] = a1l;
    g_partial[(b2 * 2 + 0) * DD + d] = a0h;
    g_partial[(b2 * 2 + 1) * DD + d] = a1h;

    // ---- last-block-per-btile reduction, single-fence discipline ----
    __syncthreads();                       // CTA sync edge: all stores "before" tid0
    if (tid == 0) {
        __threadfence();                   // release (tid0 only)
        unsigned old = atomicAdd(&g_cnt[btile], 1u);
        isLastS = ((old % DD) == (DD - 1)) ? 1u : 0u;   // monotonic: replay-safe
        if (isLastS) __threadfence();      // acquire (tid0 only)
    }
    __syncthreads();                       // CTA sync edge: publish isLastS + acquire
    if (isLastS) {
        const int obase = btile * (BT * 2);             // 512 outputs per btile
        #pragma unroll
        for (int o = tid; o < BT * 2; o += 128) {       // 4 outputs per thread
            const float4* p = reinterpret_cast<const float4*>(g_partial + (obase + o) * DD);
            float s = 0.f;
            #pragma unroll
            for (int q = 0; q < DD / 4; q++) {
                float4 x = p[q];
                s += (x.x + x.y) + (x.z + x.w);
            }
            out[obase + o] = s;
        }
    }
}

// ---------------- launch ----------------------------------------------------------
extern "C" void kernel_launch(void* const* d_in, const int* in_sizes, int n_in,
                              void* d_out, int out_size) {
    const int*   idx       = (const int*)  d_in[0];
    const float* emb_mean  = (const float*)d_in[1];
    const float* emb_std   = (const float*)d_in[2];
    const float* v         = (const float*)d_in[3];
    const float* W_ops     = (const float*)d_in[4];
    const float* W_cat     = (const float*)d_in[5];
    const float* log_alpha = (const float*)d_in[6];
    float* out = (float*)d_out;

    prep_kernel<<<PBLK, 128>>>(W_ops, W_cat, log_alpha, emb_std);
    main_kernel<<<dim3(NBT, DD), 128>>>(idx, emb_mean, v, out);
}

// round 13
// speedup vs baseline: 1.0645x; 1.0645x over previous
#include <cuda_runtime.h>
#include <math.h>

// Problem constants
#define NC    22            // columns
#define NE    12            // embeddings per column
#define DD    64            // feature dim
#define BB    2048          // batch
#define NPAIR 231           // 22 choose 2
#define NENT  253           // 22 lin/diag entries + 231 pair entries
#define TBL   (NC*NE)       // 264 table rows

typedef unsigned long long ull;

// ---------------- device scratch ----------------
__device__ float g_sp[TBL * DD];            // 0.01*softplus(emb_std), flat [t*DD+d]
__device__ float g_w[DD * NENT * 8];        // per-d lane-duplicated packed weights
__device__ float g_partial[2 * BB * 2 * DD];// partial[half][(b*2+k)][d]

// ---------------- f32x2 packed helpers (sm_100a+) ----------------
__device__ __forceinline__ ull pack2(float lo, float hi) {
    ull r; asm("mov.b64 %0, {%1, %2};" : "=l"(r) : "f"(lo), "f"(hi)); return r;
}
__device__ __forceinline__ void unpack2(ull x, float& lo, float& hi) {
    asm("mov.b64 {%0, %1}, %2;" : "=f"(lo), "=f"(hi) : "l"(x));
}
__device__ __forceinline__ ull fma2(ull a, ull b, ull c) {
    ull r; asm("fma.rn.f32x2 %0, %1, %2, %3;" : "=l"(r) : "l"(a), "l"(b), "l"(c)); return r;
}
__device__ __forceinline__ ull mul2(ull a, ull b) {
    ull r; asm("mul.rn.f32x2 %0, %1, %2;" : "=l"(r) : "l"(a), "l"(b)); return r;
}

__device__ __forceinline__ void softmax5(const float* __restrict__ log_alpha,
                                         float& w0, float& w1, float& w2,
                                         float& w3, float& w4) {
    float la[5], w[5];
    float mx = -1e30f, s = 0.f;
    #pragma unroll
    for (int z = 0; z < 5; z++) { la[z] = __ldg(log_alpha + z); mx = fmaxf(mx, la[z]); }
    #pragma unroll
    for (int z = 0; z < 5; z++) { w[z] = expf(la[z] - mx); s += w[z]; }
    float inv = 1.0f / s;
    w0 = w[0]*inv; w1 = w[1]*inv; w2 = w[2]*inv; w3 = w[3]*inv; w4 = w[4]*inv;
}

// ---------------- prep kernel (unchanged from r10) --------------------------------
#define LIN_B0   0
#define DIAG_B0  88
#define PAIR_B0  99
#define SP_B0    215
#define PBLK     347

__global__ void __launch_bounds__(128)
prep_kernel(const float* __restrict__ W_ops, const float* __restrict__ W_cat,
            const float* __restrict__ log_alpha, const float* __restrict__ emb_std) {
    const int blk = blockIdx.x;
    const int tid = threadIdx.x;

    if (blk >= SP_B0) {                              // softplus table
        int u = (blk - SP_B0) * 128 + tid;           // < TBL*DD = 16896 exactly
        float x = emb_std[u];
        g_sp[u] = 0.01f * (fmaxf(x, 0.0f) + log1pf(expf(-fabsf(x))));
        return;
    }

    float w0, w1, w2, w3, w4;
    softmax5(log_alpha, w0, w1, w2, w3, w4);
    const float2* W2 = reinterpret_cast<const float2*>(W_ops);
    const float2* C2 = reinterpret_cast<const float2*>(W_cat);

    if (blk >= PAIR_B0) {                            // pair weights: one (p,d)/thread
        int t = (blk - PAIR_B0) * 128 + tid;
        if (t >= NPAIR * DD) return;
        int d = t & 63;
        int p = t >> 6;
        int i = 0, rem = p;
        while (rem >= NC - 1 - i) { rem -= NC - 1 - i; i++; }
        int j = i + 1 + rem;

        float2 Mij = W2[((i*NC+j)*4 + 1)*DD + d];
        float2 Mji = W2[((j*NC+i)*4 + 1)*DD + d];
        float2 Xij = W2[((i*NC+j)*4 + 2)*DD + d];
        float2 Xji = W2[((j*NC+i)*4 + 2)*DD + d];
        float2 Nij = W2[((i*NC+j)*4 + 3)*DD + d];
        float2 Nji = W2[((j*NC+i)*4 + 3)*DD + d];
        float wx = w1*(Mij.x+Mji.x);
        float wy = w1*(Mij.y+Mji.y);
        float wz = 0.5f*(w2*(Xij.x+Xji.x) - w3*(Nij.x+Nji.x));
        float ww = 0.5f*(w2*(Xij.y+Xji.y) - w3*(Nij.y+Nji.y));
        float4* dst = reinterpret_cast<float4*>(g_w) + (d*NENT + NC + p) * 2;
        dst[0] = make_float4(wx, wx, wy, wy);
        dst[1] = make_float4(wz, wz, ww, ww);
        return;
    }

    if (blk >= DIAG_B0) {                            // diagonal weights
        int t = (blk - DIAG_B0) * 128 + tid;         // < NC*DD = 1408 exactly
        int d = t & 63;
        int i = t >> 6;
        float2 Mii = W2[((i*NC+i)*4 + 1)*DD + d];
        reinterpret_cast<float4*>(g_w)[(d*NENT + i) * 2 + 1] =
            make_float4(w1*Mii.x, w1*Mii.x, w1*Mii.y, w1*Mii.y);
        return;
    }

    // linear weights: 8-way stream split
    __shared__ float2 ls[8][16];
    {
        const int il = tid & 15;
        const int c  = tid >> 4;                 // stream id
        const int item = blk * 16 + il;          // < 1408 (88*16 exactly)
        const int i = item >> 6;
        const int d = item & 63;

        const float2* base;
        int stride;
        if (c < 6) {
            int o = (c >> 1) == 0 ? 0 : ((c >> 1) == 1 ? 2 : 3);   // op: P,X,N
            if ((c & 1) == 0) { base = W2 + (i*NC*4 + o)*DD + d; stride = 4*DD; }
            else              { base = W2 + (i*4 + o)*DD + d;     stride = NC*4*DD; }
        } else if (c == 6)    { base = C2 + i*NC*2*DD + d;        stride = 2*DD; }
        else                  { base = C2 + i*2*DD + DD + d;      stride = NC*2*DD; }

        float a0 = 0.f, a1 = 0.f;
        #pragma unroll
        for (int j = 0; j < NC; j++) {
            float2 q = base[j * stride];
            a0 += q.x; a1 += q.y;
        }
        float wc = (c < 2) ? w0 : (c < 4 ? 0.5f*w2 : (c < 6 ? 0.5f*w3 : w4));
        ls[c][il] = make_float2(a0 * wc, a1 * wc);
        __syncthreads();
        if (c == 0) {
            float L0 = 0.f, L1 = 0.f;
            #pragma unroll
            for (int s = 0; s < 8; s++) { L0 += ls[s][il].x; L1 += ls[s][il].y; }
            reinterpret_cast<float4*>(g_w)[(d*NENT + i) * 2] =
                make_float4(L0, L0, L1, L1);
        }
    }
}

// ---------------- main kernel: pair loop split across grid.z ----------------------
// grid: (8, 64, 2), 128 threads; 2 b per thread packed f32x2.
// z=0: diagonal terms + pairs with even pair-counter
// z=1: linear terms   + pairs with odd pair-counter
template<int PH>
__device__ __forceinline__ void pair_phase(const ull* e2, const ulonglong2* sw2,
                                           ull& A0, ull& A1) {
    // linear (PH=1) or diagonal (PH=0) terms
    #pragma unroll
    for (int i = 0; i < NC; i++) {
        if (PH == 1) {
            ulonglong2 wl = sw2[i * 2 + 0];
            A0 = fma2(e2[i], wl.x, A0);
            A1 = fma2(e2[i], wl.y, A1);
        } else {
            ulonglong2 wd = sw2[i * 2 + 1];
            ull p2 = mul2(e2[i], e2[i]);
            A0 = fma2(p2, wd.x, A0);
            A1 = fma2(p2, wd.y, A1);
        }
    }
    const ull NEG1 = 0xBF800000BF800000ULL;
    int pi = 0;
    #pragma unroll
    for (int i = 0; i < NC - 1; i++) {
        #pragma unroll
        for (int j = i + 1; j < NC; j++) {
            if ((pi & 1) == PH) {          // compile-time prune: pi is unroll-const
                ulonglong2 wm = sw2[(NC + pi) * 2 + 0];
                ulonglong2 wa = sw2[(NC + pi) * 2 + 1];
                ull p2 = mul2(e2[i], e2[j]);
                ull df = fma2(e2[j], NEG1, e2[i]);
                ull ad = df & 0x7FFFFFFF7FFFFFFFULL;
                A0 = fma2(p2, wm.x, A0);
                A1 = fma2(p2, wm.y, A1);
                A0 = fma2(ad, wa.x, A0);
                A1 = fma2(ad, wa.y, A1);
            }
            pi++;
        }
    }
}

__global__ void __launch_bounds__(128)
main_kernel(const int* __restrict__ idx, const float* __restrict__ emb_mean,
            const float* __restrict__ v) {
    const int d  = blockIdx.y;
    const int b0 = blockIdx.x * 256;
    const int ph = blockIdx.z;
    const int tid = threadIdx.x;

    __shared__ float swt[NENT * 8];
    __shared__ float mean_s[TBL];
    __shared__ float sp_s[TBL];

    {
        const float4* wp = reinterpret_cast<const float4*>(g_w) + d * NENT * 2;
        float4* s4 = reinterpret_cast<float4*>(swt);
        #pragma unroll
        for (int t = tid; t < NENT * 2; t += 128) s4[t] = wp[t];
        #pragma unroll
        for (int t = tid; t < TBL; t += 128) {
            mean_s[t] = emb_mean[t * DD + d];
            sp_s[t]   = g_sp[t * DD + d];
        }
    }
    __syncthreads();

    const int b  = b0 + tid;
    const int b2 = b + 128;
    const float vlo = v[b  * DD + d];
    const float vhi = v[b2 * DD + d];

    ull e2[NC];
    #pragma unroll
    for (int i = 0; i < NC; i++) {
        int iv  = idx[i * BB + b];
        int iv2 = idx[i * BB + b2];
        float elo = fmaf(sp_s[i * NE + iv],  vlo, mean_s[i * NE + iv]);
        float ehi = fmaf(sp_s[i * NE + iv2], vhi, mean_s[i * NE + iv2]);
        e2[i] = pack2(elo, ehi);
    }

    ull A0 = 0ULL, A1 = 0ULL;
    const ulonglong2* sw2 = reinterpret_cast<const ulonglong2*>(swt);

    if (ph == 0) pair_phase<0>(e2, sw2, A0, A1);
    else         pair_phase<1>(e2, sw2, A0, A1);

    float a0l, a0h, a1l, a1h;
    unpack2(A0, a0l, a0h);
    unpack2(A1, a1l, a1h);
    float* P = g_partial + ph * (BB * 2 * DD);
    P[(b  * 2 + 0) * DD + d] = a0l;
    P[(b  * 2 + 1) * DD + d] = a1l;
    P[(b2 * 2 + 0) * DD + d] = a0h;
    P[(b2 * 2 + 1) * DD + d] = a1h;
}

// ---------------- reduce: one warp per output, both halves ------------------------
__global__ void __launch_bounds__(256)
reduce_kernel(float* __restrict__ out) {
    int warp = (blockIdx.x * 256 + threadIdx.x) >> 5;   // 0..4095
    int lane = threadIdx.x & 31;
    const float* p0 = g_partial + warp * DD;
    const float* p1 = g_partial + BB * 2 * DD + warp * DD;
    float s = (p0[lane] + p0[lane + 32]) + (p1[lane] + p1[lane + 32]);
    #pragma unroll
    for (int o = 16; o > 0; o >>= 1)
        s += __shfl_down_sync(0xFFFFFFFFu, s, o);
    if (lane == 0) out[warp] = s;
}

// ---------------- launch ----------------------------------------------------------
extern "C" void kernel_launch(void* const* d_in, const int* in_sizes, int n_in,
                              void* d_out, int out_size) {
    const int*   idx       = (const int*)  d_in[0];
    const float* emb_mean  = (const float*)d_in[1];
    const float* emb_std   = (const float*)d_in[2];
    const float* v         = (const float*)d_in[3];
    const float* W_ops     = (const float*)d_in[4];
    const float* W_cat     = (const float*)d_in[5];
    const float* log_alpha = (const float*)d_in[6];
    float* out = (float*)d_out;

    prep_kernel<<<PBLK, 128>>>(W_ops, W_cat, log_alpha, emb_std);
    main_kernel<<<dim3(8, DD, 2), 128>>>(idx, emb_mean, v);
    reduce_kernel<<<(BB * 2) / 8, 256>>>(out);
}

// round 14
// speedup vs baseline: 1.2444x; 1.1690x over previous
#include <cuda_runtime.h>
#include <math.h>

// Problem constants
#define NC    22            // columns
#define NE    12            // embeddings per column
#define DD    64            // feature dim
#define BB    2048          // batch
#define NPAIR 231           // 22 choose 2
#define NENT  253           // 22 lin/diag entries + 231 pair entries
#define TBL   (NC*NE)       // 264 table rows

typedef unsigned long long ull;

// ---------------- device scratch ----------------
__device__ float g_spT[DD * TBL];           // transposed: [d][t] 0.01*softplus
__device__ float g_meanT[DD * TBL];         // transposed: [d][t] emb_mean
__device__ float g_vT[DD * BB];             // transposed: [d][b] noise v
__device__ float g_w[DD * NENT * 8];        // per-d lane-duplicated packed weights
__device__ float g_partial[BB * 2 * DD];    // partial[(b*2+k)][d]

// ---------------- f32x2 packed helpers (sm_100a+) ----------------
__device__ __forceinline__ ull pack2(float lo, float hi) {
    ull r; asm("mov.b64 %0, {%1, %2};" : "=l"(r) : "f"(lo), "f"(hi)); return r;
}
__device__ __forceinline__ void unpack2(ull x, float& lo, float& hi) {
    asm("mov.b64 {%0, %1}, %2;" : "=f"(lo), "=f"(hi) : "l"(x));
}
__device__ __forceinline__ ull fma2(ull a, ull b, ull c) {
    ull r; asm("fma.rn.f32x2 %0, %1, %2, %3;" : "=l"(r) : "l"(a), "l"(b), "l"(c)); return r;
}
__device__ __forceinline__ ull mul2(ull a, ull b) {
    ull r; asm("mul.rn.f32x2 %0, %1, %2;" : "=l"(r) : "l"(a), "l"(b)); return r;
}

__device__ __forceinline__ void softmax5(const float* __restrict__ log_alpha,
                                         float& w0, float& w1, float& w2,
                                         float& w3, float& w4) {
    float la[5], w[5];
    float mx = -1e30f, s = 0.f;
    #pragma unroll
    for (int z = 0; z < 5; z++) { la[z] = __ldg(log_alpha + z); mx = fmaxf(mx, la[z]); }
    #pragma unroll
    for (int z = 0; z < 5; z++) { w[z] = expf(la[z] - mx); s += w[z]; }
    float inv = 1.0f / s;
    w0 = w[0]*inv; w1 = w[1]*inv; w2 = w[2]*inv; w3 = w[3]*inv; w4 = w[4]*inv;
}

// ---------------- prep kernel --------------------------------------------------
// block layout (128 threads each):
//   [0, 88):    linear weights; 16 (i,d) items x 8 streams
//   [88, 99):   diagonal weights; one (i,d) per thread
//   [99, 330):  pair weights; ONE pair per block, tid = (half, d)
//   [330, 462): softplus + mean transpose; one (d,t) per thread
//   [462, 590): v transpose; 8 items per thread
#define LIN_B0   0
#define DIAG_B0  88
#define PAIR_B0  99
#define SPT_B0   330
#define VT_B0    462
#define PBLK     590

__global__ void __launch_bounds__(128)
prep_kernel(const float* __restrict__ W_ops, const float* __restrict__ W_cat,
            const float* __restrict__ log_alpha, const float* __restrict__ emb_std,
            const float* __restrict__ emb_mean, const float* __restrict__ v) {
    const int blk = blockIdx.x;
    const int tid = threadIdx.x;

    if (blk >= VT_B0) {                              // v transpose: [b][d] -> [d][b]
        int base = (blk - VT_B0) * 1024 + tid;
        #pragma unroll
        for (int k = 0; k < 8; k++) {
            int u = base + k * 128;                  // u = d*BB + b
            int b = u & (BB - 1);
            int d = u >> 11;
            g_vT[u] = v[b * DD + d];
        }
        return;
    }

    if (blk >= SPT_B0) {                             // softplus + mean transpose
        int u = (blk - SPT_B0) * 128 + tid;          // u = d*TBL + t, < 16896
        int d = u / TBL;
        int t = u - d * TBL;
        float x = emb_std[t * DD + d];
        g_spT[u]   = 0.01f * (fmaxf(x, 0.0f) + log1pf(expf(-fabsf(x))));
        g_meanT[u] = emb_mean[t * DD + d];
        return;
    }

    float w0, w1, w2, w3, w4;
    softmax5(log_alpha, w0, w1, w2, w3, w4);
    const float2* W2 = reinterpret_cast<const float2*>(W_ops);
    const float2* C2 = reinterpret_cast<const float2*>(W_cat);

    if (blk >= PAIR_B0) {                            // pair weights: one pair/block
        int p = blk - PAIR_B0;
        int half = tid >> 6;
        int d = tid & 63;
        int i = 0, rem = p;
        while (rem >= NC - 1 - i) { rem -= NC - 1 - i; i++; }
        int j = i + 1 + rem;
        float4* dst = reinterpret_cast<float4*>(g_w) + (d*NENT + NC + p) * 2;

        if (half == 0) {                             // product weights (2 loads)
            float2 Mij = W2[((i*NC+j)*4 + 1)*DD + d];
            float2 Mji = W2[((j*NC+i)*4 + 1)*DD + d];
            float wx = w1*(Mij.x+Mji.x);
            float wy = w1*(Mij.y+Mji.y);
            dst[0] = make_float4(wx, wx, wy, wy);
        } else {                                     // |diff| weights (4 loads)
            float2 Xij = W2[((i*NC+j)*4 + 2)*DD + d];
            float2 Xji = W2[((j*NC+i)*4 + 2)*DD + d];
            float2 Nij = W2[((i*NC+j)*4 + 3)*DD + d];
            float2 Nji = W2[((j*NC+i)*4 + 3)*DD + d];
            float wz = 0.5f*(w2*(Xij.x+Xji.x) - w3*(Nij.x+Nji.x));
            float ww = 0.5f*(w2*(Xij.y+Xji.y) - w3*(Nij.y+Nji.y));
            dst[1] = make_float4(wz, wz, ww, ww);
        }
        return;
    }

    if (blk >= DIAG_B0) {                            // diagonal weights
        int t = (blk - DIAG_B0) * 128 + tid;         // < NC*DD = 1408 exactly
        int d = t & 63;
        int i = t >> 6;
        float2 Mii = W2[((i*NC+i)*4 + 1)*DD + d];
        reinterpret_cast<float4*>(g_w)[(d*NENT + i) * 2 + 1] =
            make_float4(w1*Mii.x, w1*Mii.x, w1*Mii.y, w1*Mii.y);
        return;
    }

    // linear weights: 8-way stream split
    __shared__ float2 ls[8][16];
    {
        const int il = tid & 15;
        const int c  = tid >> 4;                 // stream id
        const int item = blk * 16 + il;          // < 1408 (88*16 exactly)
        const int i = item >> 6;
        const int d = item & 63;

        const float2* base;
        int stride;
        if (c < 6) {
            int o = (c >> 1) == 0 ? 0 : ((c >> 1) == 1 ? 2 : 3);   // op: P,X,N
            if ((c & 1) == 0) { base = W2 + (i*NC*4 + o)*DD + d; stride = 4*DD; }
            else              { base = W2 + (i*4 + o)*DD + d;     stride = NC*4*DD; }
        } else if (c == 6)    { base = C2 + i*NC*2*DD + d;        stride = 2*DD; }
        else                  { base = C2 + i*2*DD + DD + d;      stride = NC*2*DD; }

        float a0 = 0.f, a1 = 0.f;
        #pragma unroll
        for (int j = 0; j < NC; j++) {
            float2 q = base[j * stride];
            a0 += q.x; a1 += q.y;
        }
        float wc = (c < 2) ? w0 : (c < 4 ? 0.5f*w2 : (c < 6 ? 0.5f*w3 : w4));
        ls[c][il] = make_float2(a0 * wc, a1 * wc);
        __syncthreads();
        if (c == 0) {
            float L0 = 0.f, L1 = 0.f;
            #pragma unroll
            for (int s = 0; s < 8; s++) { L0 += ls[s][il].x; L1 += ls[s][il].y; }
            reinterpret_cast<float4*>(g_w)[(d*NENT + i) * 2] =
                make_float4(L0, L0, L1, L1);
        }
    }
}

// ---------------- main kernel: pairwise compute (coalesced prologue) --------------
// grid: (8, 64), 128 threads; 2 b per thread packed f32x2 (8*128*2 = 2048).
__global__ void __launch_bounds__(128)
main_kernel(const int* __restrict__ idx) {
    const int d  = blockIdx.y;
    const int b0 = blockIdx.x * 256;
    const int tid = threadIdx.x;

    __shared__ float swt[NENT * 8];
    __shared__ float mean_s[TBL];
    __shared__ float sp_s[TBL];

    {
        const float4* wp = reinterpret_cast<const float4*>(g_w) + d * NENT * 2;
        float4* s4 = reinterpret_cast<float4*>(swt);
        #pragma unroll
        for (int t = tid; t < NENT * 2; t += 128) s4[t] = wp[t];
        // coalesced table loads: 66 float4 per table (TBL*4 = 1056 bytes, 16-aligned)
        const float4* mt = reinterpret_cast<const float4*>(g_meanT + d * TBL);
        const float4* st = reinterpret_cast<const float4*>(g_spT   + d * TBL);
        if (tid < TBL / 4) {
            reinterpret_cast<float4*>(mean_s)[tid] = mt[tid];
            reinterpret_cast<float4*>(sp_s)[tid]   = st[tid];
        }
    }
    __syncthreads();

    const int b  = b0 + tid;
    const int b2 = b + 128;
    const float vlo = g_vT[d * BB + b];     // coalesced
    const float vhi = g_vT[d * BB + b2];    // coalesced

    ull e2[NC];
    #pragma unroll
    for (int i = 0; i < NC; i++) {
        int iv  = idx[i * BB + b];
        int iv2 = idx[i * BB + b2];
        float elo = fmaf(sp_s[i * NE + iv],  vlo, mean_s[i * NE + iv]);
        float ehi = fmaf(sp_s[i * NE + iv2], vhi, mean_s[i * NE + iv2]);
        e2[i] = pack2(elo, ehi);
    }

    ull A0 = 0ULL, A1 = 0ULL;
    const ulonglong2* sw2 = reinterpret_cast<const ulonglong2*>(swt);

    #pragma unroll
    for (int i = 0; i < NC; i++) {
        ulonglong2 wl = sw2[i * 2 + 0];
        ulonglong2 wd = sw2[i * 2 + 1];
        ull p2 = mul2(e2[i], e2[i]);
        A0 = fma2(e2[i], wl.x, A0);
        A1 = fma2(e2[i], wl.y, A1);
        A0 = fma2(p2,    wd.x, A0);
        A1 = fma2(p2,    wd.y, A1);
    }

    const ull NEG1 = 0xBF800000BF800000ULL;
    int pi = NC;
    #pragma unroll
    for (int i = 0; i < NC - 1; i++) {
        #pragma unroll
        for (int j = i + 1; j < NC; j++) {
            ulonglong2 wm = sw2[pi * 2 + 0];
            ulonglong2 wa = sw2[pi * 2 + 1];
            pi++;
            ull p2 = mul2(e2[i], e2[j]);
            ull df = fma2(e2[j], NEG1, e2[i]);
            ull ad = df & 0x7FFFFFFF7FFFFFFFULL;
            A0 = fma2(p2, wm.x, A0);
            A1 = fma2(p2, wm.y, A1);
            A0 = fma2(ad, wa.x, A0);
            A1 = fma2(ad, wa.y, A1);
        }
    }

    float a0l, a0h, a1l, a1h;
    unpack2(A0, a0l, a0h);
    unpack2(A1, a1l, a1h);
    g_partial[(b  * 2 + 0) * DD + d] = a0l;
    g_partial[(b  * 2 + 1) * DD + d] = a1l;
    g_partial[(b2 * 2 + 0) * DD + d] = a0h;
    g_partial[(b2 * 2 + 1) * DD + d] = a1h;
}

// ---------------- reduce: one warp per output over d ------------------------------
__global__ void __launch_bounds__(256)
reduce_kernel(float* __restrict__ out) {
    int warp = (blockIdx.x * 256 + threadIdx.x) >> 5;   // 0..4095
    int lane = threadIdx.x & 31;
    const float* p = g_partial + warp * DD;
    float s = p[lane] + p[lane + 32];
    #pragma unroll
    for (int o = 16; o > 0; o >>= 1)
        s += __shfl_down_sync(0xFFFFFFFFu, s, o);
    if (lane == 0) out[warp] = s;
}

// ---------------- launch ----------------------------------------------------------
extern "C" void kernel_launch(void* const* d_in, const int* in_sizes, int n_in,
                              void* d_out, int out_size) {
    const int*   idx       = (const int*)  d_in[0];
    const float* emb_mean  = (const float*)d_in[1];
    const float* emb_std   = (const float*)d_in[2];
    const float* v         = (const float*)d_in[3];
    const float* W_ops     = (const float*)d_in[4];
    const float* W_cat     = (const float*)d_in[5];
    const float* log_alpha = (const float*)d_in[6];
    float* out = (float*)d_out;

    prep_kernel<<<PBLK, 128>>>(W_ops, W_cat, log_alpha, emb_std, emb_mean, v);
    main_kernel<<<dim3(8, DD), 128>>>(idx);
    reduce_kernel<<<(BB * 2) / 8, 256>>>(out);
}